// round 14
// baseline (speedup 1.0000x reference)
#include <cuda_runtime.h>
#include <cuda_fp16.h>
#include <cuda_bf16.h>
#include <cstdint>

// self_attention_9225589752302 — round 13: deferred GEMM2 (interleaved with next GEMM1),
// in-kernel K transpose (prep = J/V only). 3-stage cp.async prefetch-1, log2 softmax.
// grid (16 k-tiles, 64 batches), 256 thr, 2 CTAs/SM.

#define NTHREADS 256
#define LOG2E 1.4426950408889634f

// ---- global scratch (J/V only) ----
__device__ __half g_JHi[4194304];   // [pb][c=64][j=1024]
__device__ __half g_JLo[4194304];
__device__ __half g_VH [4194304];   // [pb][c=64][j=1024] single fp16

// ---- smem layout: K 16KB | 3 stages x 24KB | LRED ----
#define KHIo 0u
#define KLOo 8192u
#define STG  16384u
#define SSZ  24576u
#define JHIo 0u
#define JLOo 8192u
#define VHo  16384u
#define LRED (16384u + 3u * 24576u)     // 90112
#define SMEM_BYTES (LRED + 1536u)
#define OSTAGE 0u                       // epilogue f32 [64][64] over K tiles
#define FSTG (STG + SSZ)                // prologue f32 K stage (in stage-1 region, 16.6KB)

static __device__ __forceinline__ uint32_t smem_u32(const void* p) {
    uint32_t a;
    asm("{ .reg .u64 t; cvta.to.shared.u64 t, %1; cvt.u32.u64 %0, t; }" : "=r"(a) : "l"(p));
    return a;
}
static __device__ __forceinline__ float ex2f(float x) {
    float r;
    asm("ex2.approx.ftz.f32 %0, %1;" : "=f"(r) : "f"(x));
    return r;
}
static __device__ __forceinline__ void cpa16(uint32_t dst, const void* src) {
    asm volatile("cp.async.cg.shared.global [%0], [%1], 16;" :: "r"(dst), "l"(src));
}
#define CP_COMMIT() asm volatile("cp.async.commit_group;" ::: "memory")
#define CP_WAIT0()  asm volatile("cp.async.wait_group 0;" ::: "memory")
static __device__ __forceinline__ void barg(int id) {
    asm volatile("bar.sync %0, 128;" :: "r"(id) : "memory");
}

static __device__ __forceinline__ void ldsm4(uint32_t r[4], uint32_t a) {
    asm volatile("ldmatrix.sync.aligned.m8n8.x4.shared.b16 {%0,%1,%2,%3}, [%4];"
        : "=r"(r[0]), "=r"(r[1]), "=r"(r[2]), "=r"(r[3]) : "r"(a));
}
static __device__ __forceinline__ void ldsm4t(uint32_t r[4], uint32_t a) {
    asm volatile("ldmatrix.sync.aligned.m8n8.x4.trans.shared.b16 {%0,%1,%2,%3}, [%4];"
        : "=r"(r[0]), "=r"(r[1]), "=r"(r[2]), "=r"(r[3]) : "r"(a));
}
static __device__ __forceinline__ void mma_f16(float d[4], const uint32_t a[4], uint32_t b0, uint32_t b1) {
    asm("mma.sync.aligned.m16n8k16.row.col.f32.f16.f16.f32 "
        "{%0,%1,%2,%3}, {%4,%5,%6,%7}, {%8,%9}, {%0,%1,%2,%3};"
        : "+f"(d[0]), "+f"(d[1]), "+f"(d[2]), "+f"(d[3])
        : "r"(a[0]), "r"(a[1]), "r"(a[2]), "r"(a[3]), "r"(b0), "r"(b1));
}
static __device__ __forceinline__ uint32_t u32h2(__half2 h) { return *(uint32_t*)&h; }

// ---- prep: J fp16 hi/lo split + V fp16 round (2 float4/thread) ----
__global__ __launch_bounds__(256)
void prep_kernel(const float* __restrict__ J, const float* __restrict__ V) {
    #pragma unroll
    for (int u = 0; u < 2; u++) {
        unsigned f = blockIdx.x * 512u + threadIdx.x + (unsigned)u * 256u;
        float4 jv = ((const float4*)J)[f];
        float4 vv = ((const float4*)V)[f];
        __half2 h0 = __floats2half2_rn(jv.x, jv.y), h1 = __floats2half2_rn(jv.z, jv.w);
        float2 a0 = __half22float2(h0), a1 = __half22float2(h1);
        __half2 l0 = __floats2half2_rn(jv.x - a0.x, jv.y - a0.y);
        __half2 l1 = __floats2half2_rn(jv.z - a1.x, jv.w - a1.y);
        ((__half2*)g_JHi)[f * 2] = h0; ((__half2*)g_JHi)[f * 2 + 1] = h1;
        ((__half2*)g_JLo)[f * 2] = l0; ((__half2*)g_JLo)[f * 2 + 1] = l1;
        ((__half2*)g_VH)[f * 2]     = __floats2half2_rn(vv.x, vv.y);
        ((__half2*)g_VH)[f * 2 + 1] = __floats2half2_rn(vv.z, vv.w);
    }
}

// ---- main kernel ----
__global__ __launch_bounds__(NTHREADS, 2)
void attn_mma_kernel(const float* __restrict__ Kg, float* __restrict__ Og) {
    extern __shared__ char smem[];
    const uint32_t smb = smem_u32(smem);
    float* lred  = (float*)(smem + LRED);
    float* msm   = lred + 192;
    float* ostage = (float*)(smem + OSTAGE);
    float* fstage = (float*)(smem + FSTG);

    const int tid  = threadIdx.x;
    const int lane = tid & 31;
    const int wid  = tid >> 5;
    const int wm   = wid & 3;
    const int wn   = wid >> 2;          // j-half group (0/1)
    const int gtid = tid & 127;
    const int m0   = wm * 16;
    const int j0   = wn * 32;
    const unsigned pbo   = (unsigned)blockIdx.y * 65536u;
    const unsigned kbase = (unsigned)blockIdx.x * 64u;

    // group-local copy addressing
    uint32_t dstoff[2];
    unsigned srcoff[2];
    #pragma unroll
    for (int t = 0; t < 2; t++) {
        int flat = gtid + t * 128;
        uint32_t c = (uint32_t)(flat >> 2), ch = (uint32_t)(flat & 3);
        uint32_t jb = (uint32_t)(wn * 64) + ch * 16u;
        dstoff[t] = c * 128u + (jb ^ ((c & 7u) << 4));
        srcoff[t] = pbo + c * 1024u + (unsigned)(wn * 32) + ch * 8u;
    }

    // ---------- prologue: K f32 load -> fstage -> transpose + split (log2e folded) ----------
    #pragma unroll
    for (int t = 0; t < 4; t++) {
        int flat = tid + t * NTHREADS;           // 1024 float4
        int c = flat >> 4, k4 = flat & 15;
        float4 v = *(const float4*)(Kg + pbo + (unsigned)c * 1024u + kbase + (unsigned)k4 * 4u);
        float* s = fstage + c * 65 + k4 * 4;
        s[0] = v.x; s[1] = v.y; s[2] = v.z; s[3] = v.w;
    }
    __syncthreads();
    #pragma unroll
    for (int t = 0; t < 8; t++) {
        int flat = tid + t * NTHREADS;           // 2048: k x c-pair
        int c = (flat & 31) * 2, k = flat >> 5;
        float x0 = fstage[c * 65 + k] * LOG2E;
        float x1 = fstage[(c + 1) * 65 + k] * LOG2E;
        __half2 h = __floats2half2_rn(x0, x1);
        float2 hb = __half22float2(h);
        __half2 l = __floats2half2_rn(x0 - hb.x, x1 - hb.y);
        uint32_t off = (uint32_t)k * 128u + ((((uint32_t)c) * 2u) ^ ((((uint32_t)k) & 7u) << 4));
        *(uint32_t*)(smem + KHIo + off) = u32h2(h);
        *(uint32_t*)(smem + KLOo + off) = u32h2(l);
    }
    __syncthreads();   // fstage (stage-1 region) free; K tiles visible

    // stage-0 copies for tile 0
    #pragma unroll
    for (int t = 0; t < 2; t++) {
        cpa16(smb + STG + JHIo + dstoff[t], g_JHi + srcoff[t]);
        cpa16(smb + STG + JLOo + dstoff[t], g_JLo + srcoff[t]);
        cpa16(smb + STG + VHo  + dstoff[t], g_VH  + srcoff[t]);
    }
    CP_COMMIT();
    CP_WAIT0();
    barg(1 + wn);

    // lane-constant address pieces
    const uint32_t xorl  = (uint32_t)(lane & 7) << 4;
    const uint32_t aRow0 = (uint32_t)(m0 + (lane & 15)) * 128u;
    const uint32_t aColH = (uint32_t)((lane >> 4) << 4);
    const uint32_t bRowJ = (uint32_t)((lane & 15)) * 128u;
    const uint32_t bColJ = (uint32_t)((lane >> 4) << 4);
    const uint32_t vRow  = (uint32_t)(lane & 7) * 128u;
    const uint32_t vColH = (uint32_t)((lane >> 3) << 4);
    const uint32_t vcol  = ((uint32_t)(j0 * 2) + vColH) ^ xorl;

    // cache K fragments in registers
    uint32_t kfh[4][4], kfl[4][4];
    #pragma unroll
    for (int ks = 0; ks < 4; ks++) {
        uint32_t acol = ((uint32_t)(ks * 32) + aColH) ^ xorl;
        ldsm4(kfh[ks], smb + KHIo + aRow0 + acol);
        ldsm4(kfl[ks], smb + KLOo + aRow0 + acol);
    }

    float D2[8][4];
    #pragma unroll
    for (int nt = 0; nt < 8; nt++)
        #pragma unroll
        for (int i = 0; i < 4; i++) D2[nt][i] = 0.0f;
    float rsum[2] = {0.0f, 0.0f};
    float mrow0 = -1e30f, mrow1 = -1e30f;

    uint32_t pprev[2][4];      // P fragments of previous iter
    float aprev0 = 1.0f, aprev1 = 1.0f;
    bool chprev = false;
    const int mybar = 1 + wn;

    for (int jt = 0; jt < 16; jt++) {
        const uint32_t cur = STG + (uint32_t)(jt % 3) * SSZ;            // J(jt), V(jt)
        const uint32_t prv = STG + (uint32_t)((jt + 2) % 3) * SSZ;      // V(jt-1)

        // issue copies for jt+1 into stage (jt+1)%3
        if (jt < 15) {
            const uint32_t nxt = STG + (uint32_t)((jt + 1) % 3) * SSZ;
            unsigned go = (unsigned)(jt + 1) * 64u;
            #pragma unroll
            for (int t = 0; t < 2; t++) {
                cpa16(smb + nxt + JHIo + dstoff[t], g_JHi + srcoff[t] + go);
                cpa16(smb + nxt + JLOo + dstoff[t], g_JLo + srcoff[t] + go);
                cpa16(smb + nxt + VHo  + dstoff[t], g_VH  + srcoff[t] + go);
            }
            CP_COMMIT();
        }

        // ---------- GEMM1(jt): S̃[16 x 32] fp16 3-pass ----------
        float S[4][4];
        #pragma unroll
        for (int nt = 0; nt < 4; nt++)
            #pragma unroll
            for (int i = 0; i < 4; i++) S[nt][i] = 0.0f;

        #pragma unroll
        for (int ks = 0; ks < 4; ks++) {
            uint32_t jrow = (uint32_t)(ks * 16) * 128u + bRowJ;
            #pragma unroll
            for (int ntp = 0; ntp < 2; ntp++) {
                uint32_t bh[4], bl[4];
                uint32_t bcol = ((uint32_t)((j0 + ntp * 16) * 2) + bColJ) ^ xorl;
                ldsm4t(bh, smb + cur + JHIo + jrow + bcol);
                ldsm4t(bl, smb + cur + JLOo + jrow + bcol);
                #pragma unroll
                for (int q = 0; q < 2; q++) {
                    int nt = 2 * ntp + q;
                    mma_f16(S[nt], kfh[ks], bh[2 * q], bh[2 * q + 1]);
                    mma_f16(S[nt], kfh[ks], bl[2 * q], bl[2 * q + 1]);
                    mma_f16(S[nt], kfl[ks], bh[2 * q], bh[2 * q + 1]);
                }
            }
        }

        // ---------- deferred GEMM2(jt-1): rescale D2, then P(jt-1) x V(jt-1) ----------
        if (jt > 0) {
            if (chprev) {
                #pragma unroll
                for (int nt = 0; nt < 8; nt++) {
                    D2[nt][0] *= aprev0; D2[nt][1] *= aprev0;
                    D2[nt][2] *= aprev1; D2[nt][3] *= aprev1;
                }
            }
            #pragma unroll
            for (int nt = 0; nt < 8; nt++) {
                uint32_t vh[4];
                uint32_t vr = (uint32_t)(nt * 8) * 128u + vRow;
                ldsm4(vh, smb + prv + VHo + vr + vcol);
                #pragma unroll
                for (int g = 0; g < 2; g++)
                    mma_f16(D2[nt], pprev[g], vh[2 * g], vh[2 * g + 1]);
            }
        }

        // ---------- softmax(jt) (log2 domain) ----------
        float mx0 = -1e30f, mx1 = -1e30f;
        #pragma unroll
        for (int nt = 0; nt < 4; nt++) {
            mx0 = fmaxf(mx0, fmaxf(S[nt][0], S[nt][1]));
            mx1 = fmaxf(mx1, fmaxf(S[nt][2], S[nt][3]));
        }
        mx0 = fmaxf(mx0, __shfl_xor_sync(0xffffffffu, mx0, 1));
        mx0 = fmaxf(mx0, __shfl_xor_sync(0xffffffffu, mx0, 2));
        mx1 = fmaxf(mx1, __shfl_xor_sync(0xffffffffu, mx1, 1));
        mx1 = fmaxf(mx1, __shfl_xor_sync(0xffffffffu, mx1, 2));
        bool changed = (mx0 > mrow0) || (mx1 > mrow1);
        chprev = __any_sync(0xffffffffu, changed);
        if (chprev) {
            float nm0 = fmaxf(mrow0, mx0), nm1 = fmaxf(mrow1, mx1);
            aprev0 = ex2f(mrow0 - nm0); aprev1 = ex2f(mrow1 - nm1);
            mrow0 = nm0; mrow1 = nm1;
            rsum[0] *= aprev0; rsum[1] *= aprev1;   // rsum rescaled immediately; D2 deferred
        } else {
            aprev0 = 1.0f; aprev1 = 1.0f;
        }

        #pragma unroll
        for (int g = 0; g < 2; g++)
            #pragma unroll
            for (int q = 0; q < 2; q++) {
                const float* s = S[2 * g + q];
                float p0 = ex2f(s[0] - mrow0), p1 = ex2f(s[1] - mrow0);
                float p2 = ex2f(s[2] - mrow1), p3 = ex2f(s[3] - mrow1);
                rsum[0] += p0 + p1;
                rsum[1] += p2 + p3;
                pprev[g][2 * q]     = u32h2(__floats2half2_rn(p0, p1));
                pprev[g][2 * q + 1] = u32h2(__floats2half2_rn(p2, p3));
            }

        if (jt < 15) CP_WAIT0();
        barg(mybar);
    }

    // ---------- final GEMM2(15): V(15) in stage 15%3=0 ----------
    {
        if (chprev) {
            #pragma unroll
            for (int nt = 0; nt < 8; nt++) {
                D2[nt][0] *= aprev0; D2[nt][1] *= aprev0;
                D2[nt][2] *= aprev1; D2[nt][3] *= aprev1;
            }
        }
        const uint32_t prv = STG + 0u * SSZ;
        #pragma unroll
        for (int nt = 0; nt < 8; nt++) {
            uint32_t vh[4];
            uint32_t vr = (uint32_t)(nt * 8) * 128u + vRow;
            ldsm4(vh, smb + prv + VHo + vr + vcol);
            #pragma unroll
            for (int g = 0; g < 2; g++)
                mma_f16(D2[nt], pprev[g], vh[2 * g], vh[2 * g + 1]);
        }
    }

    // ---------- Epilogue ----------
    const int r = m0 + (lane >> 2);
    if ((lane & 3) == 0) {
        msm[wn * 64 + r]     = mrow0;
        msm[wn * 64 + r + 8] = mrow1;
    }
    __syncthreads();
    {
        float M0 = fmaxf(msm[r], msm[64 + r]);
        float M1 = fmaxf(msm[r + 8], msm[64 + r + 8]);
        float s0 = ex2f(mrow0 - M0), s1 = ex2f(mrow1 - M1);
        rsum[0] *= s0; rsum[1] *= s1;
        #pragma unroll
        for (int nt = 0; nt < 8; nt++) {
            D2[nt][0] *= s0; D2[nt][1] *= s0;
            D2[nt][2] *= s1; D2[nt][3] *= s1;
        }
    }

    #pragma unroll
    for (int rr = 0; rr < 2; rr++) {
        float v = rsum[rr];
        v += __shfl_xor_sync(0xffffffffu, v, 1);
        v += __shfl_xor_sync(0xffffffffu, v, 2);
        if ((lane & 3) == 0)
            lred[wn * 64 + m0 + rr * 8 + (lane >> 2)] = v;
    }
    __syncthreads();
    if (tid < 64) lred[128 + tid] = 1.0f / (lred[tid] + lred[64 + tid]);

    if (wn == 0) {
        #pragma unroll
        for (int nt = 0; nt < 8; nt++) {
            int c0 = nt * 8 + 2 * (lane & 3);
            int rw = m0 + (lane >> 2);
            ostage[c0 * 64 + rw]           = D2[nt][0];
            ostage[(c0 + 1) * 64 + rw]     = D2[nt][1];
            ostage[c0 * 64 + rw + 8]       = D2[nt][2];
            ostage[(c0 + 1) * 64 + rw + 8] = D2[nt][3];
        }
    }
    __syncthreads();
    if (wn == 1) {
        #pragma unroll
        for (int nt = 0; nt < 8; nt++) {
            int c0 = nt * 8 + 2 * (lane & 3);
            int rw = m0 + (lane >> 2);
            ostage[c0 * 64 + rw]           += D2[nt][0];
            ostage[(c0 + 1) * 64 + rw]     += D2[nt][1];
            ostage[c0 * 64 + rw + 8]       += D2[nt][2];
            ostage[(c0 + 1) * 64 + rw + 8] += D2[nt][3];
        }
    }
    __syncthreads();

    #pragma unroll
    for (int t = 0; t < 4; t++) {
        int flat = tid + t * NTHREADS;
        int c = flat >> 4, k4 = flat & 15;
        float4 v  = *(float4*)(ostage + c * 64 + k4 * 4);
        float4 iv = *(float4*)(lred + 128 + k4 * 4);
        v.x *= iv.x; v.y *= iv.y; v.z *= iv.z; v.w *= iv.w;
        *(float4*)(Og + pbo + (unsigned)c * 1024u + kbase + (unsigned)k4 * 4u) = v;
    }
}

extern "C" void kernel_launch(void* const* d_in, const int* in_sizes, int n_in,
                              void* d_out, int out_size) {
    const float* Kg = (const float*)d_in[0];
    const float* Jg = (const float*)d_in[1];
    const float* Vg = (const float*)d_in[2];
    float* Og = (float*)d_out;

    prep_kernel<<<2048, 256>>>(Jg, Vg);

    cudaFuncSetAttribute(attn_mma_kernel,
                         cudaFuncAttributeMaxDynamicSharedMemorySize, SMEM_BYTES);
    dim3 grid(16, 64);
    attn_mma_kernel<<<grid, NTHREADS, SMEM_BYTES>>>(Kg, Og);
}

// round 15
// speedup vs baseline: 1.0471x; 1.0471x over previous
#include <cuda_runtime.h>
#include <cuda_fp16.h>
#include <cuda_bf16.h>
#include <cstdint>

// self_attention_9225589752302 — round 14: R11 main kernel + elementwise-only prep;
// K^T materialized via ldmatrix.trans from [c][k]-layout smem (no transpose anywhere).
// GEMM1 fp16 hi/lo 3-pass (log2 domain), GEMM2 fp16 1-pass, 3-stage cp.async.
// grid (16 k-tiles, 64 batches), 256 thr, 2 CTAs/SM.

#define NTHREADS 256
#define LOG2E 1.4426950408889634f

// ---- global scratch (all elementwise layouts) ----
__device__ __half g_KHi[4194304];   // [pb][c=64][k=1024], pre-scaled by log2e
__device__ __half g_KLo[4194304];
__device__ __half g_JHi[4194304];   // [pb][c=64][j=1024]
__device__ __half g_JLo[4194304];
__device__ __half g_VH [4194304];   // [pb][c=64][j=1024] single fp16

// ---- smem layout: K 16KB | 3 stages x 24KB | LRED ----
#define KHIo 0u            // K [c=64 rows x 128B of k] fp16, swz ((c&7)<<4)
#define KLOo 8192u
#define STG  16384u
#define SSZ  24576u
#define JHIo 0u
#define JLOo 8192u
#define VHo  16384u
#define LRED (16384u + 3u * 24576u)     // 90112
#define SMEM_BYTES (LRED + 1536u)
#define OSTAGE 0u

static __device__ __forceinline__ uint32_t smem_u32(const void* p) {
    uint32_t a;
    asm("{ .reg .u64 t; cvta.to.shared.u64 t, %1; cvt.u32.u64 %0, t; }" : "=r"(a) : "l"(p));
    return a;
}
static __device__ __forceinline__ float ex2f(float x) {
    float r;
    asm("ex2.approx.ftz.f32 %0, %1;" : "=f"(r) : "f"(x));
    return r;
}
static __device__ __forceinline__ void cpa16(uint32_t dst, const void* src) {
    asm volatile("cp.async.cg.shared.global [%0], [%1], 16;" :: "r"(dst), "l"(src));
}
#define CP_COMMIT() asm volatile("cp.async.commit_group;" ::: "memory")
#define CP_WAIT1()  asm volatile("cp.async.wait_group 1;" ::: "memory")
#define CP_WAIT0()  asm volatile("cp.async.wait_group 0;" ::: "memory")

static __device__ __forceinline__ void ldsm4t(uint32_t r[4], uint32_t a) {
    asm volatile("ldmatrix.sync.aligned.m8n8.x4.trans.shared.b16 {%0,%1,%2,%3}, [%4];"
        : "=r"(r[0]), "=r"(r[1]), "=r"(r[2]), "=r"(r[3]) : "r"(a));
}
static __device__ __forceinline__ void ldsm4(uint32_t r[4], uint32_t a) {
    asm volatile("ldmatrix.sync.aligned.m8n8.x4.shared.b16 {%0,%1,%2,%3}, [%4];"
        : "=r"(r[0]), "=r"(r[1]), "=r"(r[2]), "=r"(r[3]) : "r"(a));
}
static __device__ __forceinline__ void mma_f16(float d[4], const uint32_t a[4], uint32_t b0, uint32_t b1) {
    asm("mma.sync.aligned.m16n8k16.row.col.f32.f16.f16.f32 "
        "{%0,%1,%2,%3}, {%4,%5,%6,%7}, {%8,%9}, {%0,%1,%2,%3};"
        : "+f"(d[0]), "+f"(d[1]), "+f"(d[2]), "+f"(d[3])
        : "r"(a[0]), "r"(a[1]), "r"(a[2]), "r"(a[3]), "r"(b0), "r"(b1));
}
static __device__ __forceinline__ uint32_t u32h2(__half2 h) { return *(uint32_t*)&h; }

// ---- prep: pure elementwise. 2 float4 per tensor per thread -> 16B stores ----
__global__ __launch_bounds__(256)
void prep_kernel(const float4* __restrict__ K4, const float4* __restrict__ J4,
                 const float4* __restrict__ V4) {
    unsigned b = blockIdx.x * 256u + threadIdx.x;   // uint4 (16B) output index
    unsigned f = b * 2u;
    // J hi/lo
    float4 ja = J4[f], jb = J4[f + 1];
    __half2 jh0 = __floats2half2_rn(ja.x, ja.y), jh1 = __floats2half2_rn(ja.z, ja.w);
    __half2 jh2 = __floats2half2_rn(jb.x, jb.y), jh3 = __floats2half2_rn(jb.z, jb.w);
    float2 a0 = __half22float2(jh0), a1 = __half22float2(jh1);
    float2 a2 = __half22float2(jh2), a3 = __half22float2(jh3);
    __half2 jl0 = __floats2half2_rn(ja.x - a0.x, ja.y - a0.y);
    __half2 jl1 = __floats2half2_rn(ja.z - a1.x, ja.w - a1.y);
    __half2 jl2 = __floats2half2_rn(jb.x - a2.x, jb.y - a2.y);
    __half2 jl3 = __floats2half2_rn(jb.z - a3.x, jb.w - a3.y);
    ((uint4*)g_JHi)[b] = make_uint4(u32h2(jh0), u32h2(jh1), u32h2(jh2), u32h2(jh3));
    ((uint4*)g_JLo)[b] = make_uint4(u32h2(jl0), u32h2(jl1), u32h2(jl2), u32h2(jl3));
    // V single fp16
    float4 va = V4[f], vb = V4[f + 1];
    ((uint4*)g_VH)[b] = make_uint4(
        u32h2(__floats2half2_rn(va.x, va.y)), u32h2(__floats2half2_rn(va.z, va.w)),
        u32h2(__floats2half2_rn(vb.x, vb.y)), u32h2(__floats2half2_rn(vb.z, vb.w)));
    // K * log2e hi/lo
    float4 ka = K4[f], kb = K4[f + 1];
    ka.x *= LOG2E; ka.y *= LOG2E; ka.z *= LOG2E; ka.w *= LOG2E;
    kb.x *= LOG2E; kb.y *= LOG2E; kb.z *= LOG2E; kb.w *= LOG2E;
    __half2 kh0 = __floats2half2_rn(ka.x, ka.y), kh1 = __floats2half2_rn(ka.z, ka.w);
    __half2 kh2 = __floats2half2_rn(kb.x, kb.y), kh3 = __floats2half2_rn(kb.z, kb.w);
    float2 c0 = __half22float2(kh0), c1 = __half22float2(kh1);
    float2 c2 = __half22float2(kh2), c3 = __half22float2(kh3);
    __half2 kl0 = __floats2half2_rn(ka.x - c0.x, ka.y - c0.y);
    __half2 kl1 = __floats2half2_rn(ka.z - c1.x, ka.w - c1.y);
    __half2 kl2 = __floats2half2_rn(kb.x - c2.x, kb.y - c2.y);
    __half2 kl3 = __floats2half2_rn(kb.z - c3.x, kb.w - c3.y);
    ((uint4*)g_KHi)[b] = make_uint4(u32h2(kh0), u32h2(kh1), u32h2(kh2), u32h2(kh3));
    ((uint4*)g_KLo)[b] = make_uint4(u32h2(kl0), u32h2(kl1), u32h2(kl2), u32h2(kl3));
}

// ---- main kernel (R11 body; K frags via ldsm4t) ----
__global__ __launch_bounds__(NTHREADS, 2)
void attn_mma_kernel(float* __restrict__ Og) {
    extern __shared__ char smem[];
    const uint32_t smb = smem_u32(smem);
    float* lred  = (float*)(smem + LRED);
    float* msm   = lred + 192;
    float* ostage = (float*)(smem + OSTAGE);

    const int tid  = threadIdx.x;
    const int lane = tid & 31;
    const int wid  = tid >> 5;
    const int wm   = wid & 3;
    const int wn   = wid >> 2;
    const int m0   = wm * 16;
    const int j0   = wn * 32;
    const unsigned pbo   = (unsigned)blockIdx.y * 65536u;
    const unsigned kbase = (unsigned)blockIdx.x * 64u;

    // hoisted copy addressing: 2 chunks per thread (c-row, 16B k/j-chunk)
    uint32_t dstoff[2];
    unsigned srcoff[2];
    #pragma unroll
    for (int t = 0; t < 2; t++) {
        int flat = tid + t * NTHREADS;
        uint32_t c = (uint32_t)(flat >> 3), ch = (uint32_t)(flat & 7);
        dstoff[t] = c * 128u + ((ch * 16u) ^ ((c & 7u) << 4));
        srcoff[t] = pbo + c * 1024u + ch * 8u;
    }

    // ---------- prologue: K tile ([c][k] layout) + stages 0,1 ----------
    #pragma unroll
    for (int t = 0; t < 2; t++) {
        cpa16(smb + KHIo + dstoff[t], g_KHi + srcoff[t] + kbase);
        cpa16(smb + KLOo + dstoff[t], g_KLo + srcoff[t] + kbase);
    }
    #pragma unroll
    for (int t = 0; t < 2; t++) {
        cpa16(smb + STG + JHIo + dstoff[t], g_JHi + srcoff[t]);
        cpa16(smb + STG + JLOo + dstoff[t], g_JLo + srcoff[t]);
        cpa16(smb + STG + VHo  + dstoff[t], g_VH  + srcoff[t]);
    }
    CP_COMMIT();
    #pragma unroll
    for (int t = 0; t < 2; t++) {
        cpa16(smb + STG + SSZ + JHIo + dstoff[t], g_JHi + srcoff[t] + 64u);
        cpa16(smb + STG + SSZ + JLOo + dstoff[t], g_JLo + srcoff[t] + 64u);
        cpa16(smb + STG + SSZ + VHo  + dstoff[t], g_VH  + srcoff[t] + 64u);
    }
    CP_COMMIT();
    CP_WAIT1();   // K + stage0 complete
    __syncthreads();

    // lane-constant address pieces
    const uint32_t xorl  = (uint32_t)(lane & 7) << 4;
    const uint32_t bRowJ = (uint32_t)((lane & 15)) * 128u;
    const uint32_t bColJ = (uint32_t)((lane >> 4) << 4);
    const uint32_t vRow  = (uint32_t)(lane & 7) * 128u;
    const uint32_t vColH = (uint32_t)((lane >> 3) << 4);
    const uint32_t vcol  = ((uint32_t)(j0 * 2) + vColH) ^ xorl;
    // A-operand trans-load addressing (from [c][k] layout):
    // lane -> c-row (lane&7)+((lane>>4)<<3), k-byte chunk m0*2 + ((lane>>3)&1)*16
    const uint32_t aRowT = ((uint32_t)((lane & 7) + ((lane >> 4) << 3))) * 128u;
    const uint32_t aColT = (((uint32_t)(m0 * 2)) + ((((uint32_t)lane >> 3) & 1u) << 4)) ^ xorl;

    // ---------- cache K fragments in registers (via ldsm trans) ----------
    uint32_t kfh[4][4], kfl[4][4];
    #pragma unroll
    for (int ks = 0; ks < 4; ks++) {
        uint32_t base = (uint32_t)(ks * 16) * 128u + aRowT + aColT;
        ldsm4t(kfh[ks], smb + KHIo + base);
        ldsm4t(kfl[ks], smb + KLOo + base);
    }

    float D2[8][4];
    #pragma unroll
    for (int nt = 0; nt < 8; nt++)
        #pragma unroll
        for (int i = 0; i < 4; i++) D2[nt][i] = 0.0f;
    float rsum[2] = {0.0f, 0.0f};
    float mrow0 = -1e30f, mrow1 = -1e30f;

    uint32_t curst = 0;

    for (int jt = 0; jt < 16; jt++) {
        const uint32_t cur = STG + curst * SSZ;

        // issue copies for jt+2 into stage (curst+2)%3
        if (jt < 14) {
            uint32_t ns = curst + 2u; if (ns >= 3u) ns -= 3u;
            const uint32_t nxt = STG + ns * SSZ;
            unsigned go = (unsigned)(jt + 2) * 64u;
            #pragma unroll
            for (int t = 0; t < 2; t++) {
                cpa16(smb + nxt + JHIo + dstoff[t], g_JHi + srcoff[t] + go);
                cpa16(smb + nxt + JLOo + dstoff[t], g_JLo + srcoff[t] + go);
                cpa16(smb + nxt + VHo  + dstoff[t], g_VH  + srcoff[t] + go);
            }
            CP_COMMIT();
        }

        // ---------- GEMM1: S̃[16 x 32] (log2 domain) fp16 3-pass ----------
        float S[4][4];
        #pragma unroll
        for (int nt = 0; nt < 4; nt++)
            #pragma unroll
            for (int i = 0; i < 4; i++) S[nt][i] = 0.0f;

        #pragma unroll
        for (int ks = 0; ks < 4; ks++) {
            uint32_t jrow = (uint32_t)(ks * 16) * 128u + bRowJ;
            #pragma unroll
            for (int ntp = 0; ntp < 2; ntp++) {
                uint32_t bh[4], bl[4];
                uint32_t bcol = ((uint32_t)((j0 + ntp * 16) * 2) + bColJ) ^ xorl;
                ldsm4t(bh, smb + cur + JHIo + jrow + bcol);
                ldsm4t(bl, smb + cur + JLOo + jrow + bcol);
                #pragma unroll
                for (int q = 0; q < 2; q++) {
                    int nt = 2 * ntp + q;
                    mma_f16(S[nt], kfh[ks], bh[2 * q], bh[2 * q + 1]);
                    mma_f16(S[nt], kfh[ks], bl[2 * q], bl[2 * q + 1]);
                    mma_f16(S[nt], kfl[ks], bh[2 * q], bh[2 * q + 1]);
                }
            }
        }

        // ---------- online softmax (log2 domain) ----------
        float mx0 = -1e30f, mx1 = -1e30f;
        #pragma unroll
        for (int nt = 0; nt < 4; nt++) {
            mx0 = fmaxf(mx0, fmaxf(S[nt][0], S[nt][1]));
            mx1 = fmaxf(mx1, fmaxf(S[nt][2], S[nt][3]));
        }
        mx0 = fmaxf(mx0, __shfl_xor_sync(0xffffffffu, mx0, 1));
        mx0 = fmaxf(mx0, __shfl_xor_sync(0xffffffffu, mx0, 2));
        mx1 = fmaxf(mx1, __shfl_xor_sync(0xffffffffu, mx1, 1));
        mx1 = fmaxf(mx1, __shfl_xor_sync(0xffffffffu, mx1, 2));
        bool changed = (mx0 > mrow0) || (mx1 > mrow1);
        if (__any_sync(0xffffffffu, changed)) {
            float nm0 = fmaxf(mrow0, mx0), nm1 = fmaxf(mrow1, mx1);
            float a0 = ex2f(mrow0 - nm0), a1 = ex2f(mrow1 - nm1);
            mrow0 = nm0; mrow1 = nm1;
            rsum[0] *= a0; rsum[1] *= a1;
            #pragma unroll
            for (int nt = 0; nt < 8; nt++) {
                D2[nt][0] *= a0; D2[nt][1] *= a0;
                D2[nt][2] *= a1; D2[nt][3] *= a1;
            }
        }

        uint32_t phi[2][4];
        #pragma unroll
        for (int g = 0; g < 2; g++)
            #pragma unroll
            for (int q = 0; q < 2; q++) {
                const float* s = S[2 * g + q];
                float p0 = ex2f(s[0] - mrow0), p1 = ex2f(s[1] - mrow0);
                float p2 = ex2f(s[2] - mrow1), p3 = ex2f(s[3] - mrow1);
                rsum[0] += p0 + p1;
                rsum[1] += p2 + p3;
                phi[g][2 * q]     = u32h2(__floats2half2_rn(p0, p1));
                phi[g][2 * q + 1] = u32h2(__floats2half2_rn(p2, p3));
            }

        // ---------- GEMM2: D2 += P x V^T, fp16 1-pass ----------
        #pragma unroll
        for (int nt = 0; nt < 8; nt++) {
            uint32_t vh[4];
            uint32_t vr = (uint32_t)(nt * 8) * 128u + vRow;
            ldsm4(vh, smb + cur + VHo + vr + vcol);
            #pragma unroll
            for (int g = 0; g < 2; g++)
                mma_f16(D2[nt], phi[g], vh[2 * g], vh[2 * g + 1]);
        }

        if (jt < 14) { CP_WAIT1(); }
        else if (jt == 14) { CP_WAIT0(); }
        __syncthreads();
        curst = (curst == 2u) ? 0u : curst + 1u;
    }

    // ---------- Epilogue: reconcile maxes across the two j-half warps ----------
    const int r = m0 + (lane >> 2);
    if ((lane & 3) == 0) {
        msm[wn * 64 + r]     = mrow0;
        msm[wn * 64 + r + 8] = mrow1;
    }
    __syncthreads();
    {
        float M0 = fmaxf(msm[r], msm[64 + r]);
        float M1 = fmaxf(msm[r + 8], msm[64 + r + 8]);
        float s0 = ex2f(mrow0 - M0), s1 = ex2f(mrow1 - M1);
        rsum[0] *= s0; rsum[1] *= s1;
        #pragma unroll
        for (int nt = 0; nt < 8; nt++) {
            D2[nt][0] *= s0; D2[nt][1] *= s0;
            D2[nt][2] *= s1; D2[nt][3] *= s1;
        }
    }

    #pragma unroll
    for (int rr = 0; rr < 2; rr++) {
        float v = rsum[rr];
        v += __shfl_xor_sync(0xffffffffu, v, 1);
        v += __shfl_xor_sync(0xffffffffu, v, 2);
        if ((lane & 3) == 0)
            lred[wn * 64 + m0 + rr * 8 + (lane >> 2)] = v;
    }
    __syncthreads();
    if (tid < 64) lred[128 + tid] = 1.0f / (lred[tid] + lred[64 + tid]);

    if (wn == 0) {
        #pragma unroll
        for (int nt = 0; nt < 8; nt++) {
            int c0 = nt * 8 + 2 * (lane & 3);
            int rw = m0 + (lane >> 2);
            ostage[c0 * 64 + rw]           = D2[nt][0];
            ostage[(c0 + 1) * 64 + rw]     = D2[nt][1];
            ostage[c0 * 64 + rw + 8]       = D2[nt][2];
            ostage[(c0 + 1) * 64 + rw + 8] = D2[nt][3];
        }
    }
    __syncthreads();
    if (wn == 1) {
        #pragma unroll
        for (int nt = 0; nt < 8; nt++) {
            int c0 = nt * 8 + 2 * (lane & 3);
            int rw = m0 + (lane >> 2);
            ostage[c0 * 64 + rw]           += D2[nt][0];
            ostage[(c0 + 1) * 64 + rw]     += D2[nt][1];
            ostage[c0 * 64 + rw + 8]       += D2[nt][2];
            ostage[(c0 + 1) * 64 + rw + 8] += D2[nt][3];
        }
    }
    __syncthreads();

    #pragma unroll
    for (int t = 0; t < 4; t++) {
        int flat = tid + t * NTHREADS;
        int c = flat >> 4, k4 = flat & 15;
        float4 v  = *(float4*)(ostage + c * 64 + k4 * 4);
        float4 iv = *(float4*)(lred + 128 + k4 * 4);
        v.x *= iv.x; v.y *= iv.y; v.z *= iv.z; v.w *= iv.w;
        *(float4*)(Og + pbo + (unsigned)c * 1024u + kbase + (unsigned)k4 * 4u) = v;
    }
}

extern "C" void kernel_launch(void* const* d_in, const int* in_sizes, int n_in,
                              void* d_out, int out_size) {
    const float* Kg = (const float*)d_in[0];
    const float* Jg = (const float*)d_in[1];
    const float* Vg = (const float*)d_in[2];
    float* Og = (float*)d_out;

    prep_kernel<<<2048, 256>>>((const float4*)Kg, (const float4*)Jg, (const float4*)Vg);

    cudaFuncSetAttribute(attn_mma_kernel,
                         cudaFuncAttributeMaxDynamicSharedMemorySize, SMEM_BYTES);
    dim3 grid(16, 64);
    attn_mma_kernel<<<grid, NTHREADS, SMEM_BYTES>>>(Og);
}